// round 1
// baseline (speedup 1.0000x reference)
#include <cuda_runtime.h>
#include <cstdint>

#define BB 2
#define MM 2048
#define RR 256
#define HH 16
#define DHH 64
#define DD (HH*DHH)

// Scratch for projected q/k/v in (b,h,m,dh) layout, fp32.
__device__ float g_q[BB*HH*MM*DHH];
__device__ float g_k[BB*HH*MM*DHH];
__device__ float g_v[BB*HH*MM*DHH];

// ---------------- packed f32x2 helpers (Blackwell-only FFMA2 path) ----------
__device__ __forceinline__ uint64_t pack2(float x) {
    uint64_t r; uint32_t u = __float_as_uint(x);
    asm("mov.b64 %0, {%1, %1};" : "=l"(r) : "r"(u));
    return r;
}
__device__ __forceinline__ uint64_t packxy(float x, float y) {
    uint64_t r;
    asm("mov.b64 %0, {%1, %2};" : "=l"(r) : "r"(__float_as_uint(x)), "r"(__float_as_uint(y)));
    return r;
}
__device__ __forceinline__ uint64_t fma2(uint64_t a, uint64_t b, uint64_t c) {
    uint64_t d;
    asm("fma.rn.f32x2 %0, %1, %2, %3;" : "=l"(d) : "l"(a), "l"(b), "l"(c));
    return d;
}
__device__ __forceinline__ uint64_t add2(uint64_t a, uint64_t b) {
    uint64_t d;
    asm("add.rn.f32x2 %0, %1, %2;" : "=l"(d) : "l"(a), "l"(b));
    return d;
}
__device__ __forceinline__ float f2lo(uint64_t v) { return __uint_as_float((uint32_t)v); }
__device__ __forceinline__ float f2hi(uint64_t v) { return __uint_as_float((uint32_t)(v >> 32)); }

// ---------------------------------------------------------------------------
// Projection kernel: X = P(4096x256) @ V(256x1024) + bias, then RoPE (q,k) and
// scatter into (b,h,m,dh) scratch. One 64x64 output tile per CTA; the 64-wide
// N tile is exactly one head, so RoPE pairing (dh, dh+32) stays in-thread.
// Thread owns cols {2tx, 2tx+1, 2tx+32, 2tx+33} x 4 rows.
// ---------------------------------------------------------------------------
__global__ __launch_bounds__(256) void proj_kernel(
    const float* __restrict__ Pq, const float* __restrict__ Pk, const float* __restrict__ Pv,
    const float* __restrict__ Vq, const float* __restrict__ Vk, const float* __restrict__ Vv,
    const float* __restrict__ bq, const float* __restrict__ bk, const float* __restrict__ bv,
    const int* __restrict__ pos_ids)
{
    const int z = blockIdx.z;
    const float* P    = (z == 0) ? Pq : (z == 1) ? Pk : Pv;
    const float* V    = (z == 0) ? Vq : (z == 1) ? Vk : Vv;
    const float* bias = (z == 0) ? bq : (z == 1) ? bk : bv;
    float* dst        = (z == 0) ? g_q : (z == 1) ? g_k : g_v;

    __shared__ float As[32][65];   // [k][row], padded: conflict-free stores
    __shared__ float Bs[32][64];   // [k][col]

    const int tid = threadIdx.x;
    const int tx = tid & 15, ty = tid >> 4;
    const int n0 = blockIdx.x * 64;           // head = blockIdx.x
    const int m0 = blockIdx.y * 64;           // row base within B*M

    uint64_t c2[4][2];
    #pragma unroll
    for (int i = 0; i < 4; i++) { c2[i][0] = 0ull; c2[i][1] = 0ull; }

    for (int k0 = 0; k0 < RR; k0 += 32) {
        #pragma unroll
        for (int e = 0; e < 8; e++) {
            int idx = e * 256 + tid;
            int r = idx >> 5, c = idx & 31;
            As[c][r] = P[(size_t)(m0 + r) * RR + k0 + c];
        }
        #pragma unroll
        for (int e = 0; e < 8; e++) {
            int idx = e * 256 + tid;
            int kk = idx >> 6, nn = idx & 63;
            Bs[kk][nn] = V[(size_t)(k0 + kk) * DD + n0 + nn];
        }
        __syncthreads();

        #pragma unroll
        for (int k = 0; k < 32; k++) {
            const uint64_t* brow = (const uint64_t*)&Bs[k][0];
            uint64_t b20 = brow[tx];
            uint64_t b21 = brow[tx + 16];
            #pragma unroll
            for (int i = 0; i < 4; i++) {
                uint64_t aa = pack2(As[k][ty * 4 + i]);
                c2[i][0] = fma2(aa, b20, c2[i][0]);
                c2[i][1] = fma2(aa, b21, c2[i][1]);
            }
        }
        __syncthreads();
    }

    // Epilogue: bias + RoPE + scatter to (b,h,m,dh)
    const int col0 = 2 * tx;                 // 0..30
    const float bi0 = bias[n0 + col0];
    const float bi1 = bias[n0 + col0 + 1];
    const float bi2 = bias[n0 + col0 + 32];
    const float bi3 = bias[n0 + col0 + 33];
    const float Lc = 0.41524101186092033f;   // log2(10000)/32
    const float inva = exp2f(-(float)col0 * Lc);
    const float invb = exp2f(-(float)(col0 + 1) * Lc);
    const int h = blockIdx.x;

    #pragma unroll
    for (int i = 0; i < 4; i++) {
        int row = m0 + ty * 4 + i;           // 0..4095
        int b = row >> 11;                   // / M (M=2048)
        int m = row & (MM - 1);
        float x0a = f2lo(c2[i][0]) + bi0;
        float x0b = f2hi(c2[i][0]) + bi1;
        float x1a = f2lo(c2[i][1]) + bi2;
        float x1b = f2hi(c2[i][1]) + bi3;
        float* o = dst + ((size_t)(b * HH + h) * MM + m) * DHH;
        if (z == 2) {
            o[col0] = x0a; o[col0 + 1] = x0b; o[col0 + 32] = x1a; o[col0 + 33] = x1b;
        } else {
            float pos = (float)pos_ids[row];
            float sa, ca, sb, cb;
            sincosf(pos * inva, &sa, &ca);
            sincosf(pos * invb, &sb, &cb);
            o[col0]      = x0a * ca - x1a * sa;
            o[col0 + 1]  = x0b * cb - x1b * sb;
            o[col0 + 32] = x0a * sa + x1a * ca;
            o[col0 + 33] = x0b * sb + x1b * cb;
        }
    }
}

// ---------------------------------------------------------------------------
// Flash attention: thread-per-query-row online softmax.
// grid = (B*H, M/128), 128 threads. K/V staged in smem 64-row tiles; rows are
// broadcast-read (all lanes same address -> conflict-free). q and acc held as
// packed f32x2 in registers. Running-max update branch has the same FMA cost
// as the common path, so divergence is cheap and rare (~ln N events/row).
// ---------------------------------------------------------------------------
__global__ __launch_bounds__(128) void attn_kernel(const int* __restrict__ amask,
                                                   float* __restrict__ out)
{
    __shared__ __align__(16) float Ks[64][64];
    __shared__ __align__(16) float Vs[64][64];
    __shared__ int maskS[64];

    const int bh = blockIdx.x;               // b*H + h
    const int b = bh >> 4;
    const int tid = threadIdx.x;
    const int m = blockIdx.y * 128 + tid;

    const float scale = 0.125f;              // 1/sqrt(64)
    const float* qp = g_q + ((size_t)bh * MM + m) * DHH;

    uint64_t q2[32];
    #pragma unroll
    for (int i = 0; i < 16; i++) {
        float4 v = ((const float4*)qp)[i];
        q2[2 * i]     = packxy(v.x * scale, v.y * scale);
        q2[2 * i + 1] = packxy(v.z * scale, v.w * scale);
    }

    uint64_t acc2[32];
    #pragma unroll
    for (int i = 0; i < 32; i++) acc2[i] = 0ull;
    float mi = -__int_as_float(0x7f800000);  // -inf
    float l = 0.0f;

    const float* kbase = g_k + (size_t)bh * MM * DHH;
    const float* vbase = g_v + (size_t)bh * MM * DHH;

    for (int n0 = 0; n0 < MM; n0 += 64) {
        __syncthreads();
        const float4* ksrc = (const float4*)(kbase + (size_t)n0 * DHH);
        const float4* vsrc = (const float4*)(vbase + (size_t)n0 * DHH);
        float4* kdst = (float4*)&Ks[0][0];
        float4* vdst = (float4*)&Vs[0][0];
        #pragma unroll
        for (int e = 0; e < 8; e++) {
            kdst[e * 128 + tid] = ksrc[e * 128 + tid];
            vdst[e * 128 + tid] = vsrc[e * 128 + tid];
        }
        if (tid < 64) maskS[tid] = amask[b * MM + n0 + tid];
        __syncthreads();

        #pragma unroll 2
        for (int n = 0; n < 64; n++) {
            if (maskS[n] == 0) continue;
            const ulonglong2* krow = (const ulonglong2*)&Ks[n][0];
            uint64_t s0 = 0ull, s1 = 0ull, s2 = 0ull, s3 = 0ull;
            #pragma unroll
            for (int j = 0; j < 16; j += 2) {
                ulonglong2 ka = krow[j];
                ulonglong2 kb = krow[j + 1];
                s0 = fma2(q2[2 * j],     ka.x, s0);
                s1 = fma2(q2[2 * j + 1], ka.y, s1);
                s2 = fma2(q2[2 * j + 2], kb.x, s2);
                s3 = fma2(q2[2 * j + 3], kb.y, s3);
            }
            uint64_t t = add2(add2(s0, s1), add2(s2, s3));
            float sc = f2lo(t) + f2hi(t);

            const ulonglong2* vrow = (const ulonglong2*)&Vs[n][0];
            if (sc > mi) {
                float alpha = __expf(mi - sc);
                mi = sc;
                l = l * alpha + 1.0f;
                uint64_t aa = pack2(alpha);
                #pragma unroll
                for (int j = 0; j < 16; j++) {
                    ulonglong2 vv = vrow[j];
                    acc2[2 * j]     = fma2(acc2[2 * j],     aa, vv.x);
                    acc2[2 * j + 1] = fma2(acc2[2 * j + 1], aa, vv.y);
                }
            } else {
                float p = __expf(sc - mi);
                l += p;
                uint64_t pp = pack2(p);
                #pragma unroll
                for (int j = 0; j < 16; j++) {
                    ulonglong2 vv = vrow[j];
                    acc2[2 * j]     = fma2(pp, vv.x, acc2[2 * j]);
                    acc2[2 * j + 1] = fma2(pp, vv.y, acc2[2 * j + 1]);
                }
            }
        }
    }

    float inv = (l > 0.0f) ? (1.0f / l) : 0.0f;
    float* op = out + ((size_t)bh * MM + m) * DHH;
    #pragma unroll
    for (int j = 0; j < 32; j++) {
        ((float2*)op)[j] = make_float2(f2lo(acc2[j]) * inv, f2hi(acc2[j]) * inv);
    }
}

extern "C" void kernel_launch(void* const* d_in, const int* in_sizes, int n_in,
                              void* d_out, int out_size) {
    const float* Pq = (const float*)d_in[0];
    const float* Pk = (const float*)d_in[1];
    const float* Pv = (const float*)d_in[2];
    const float* Vq = (const float*)d_in[3];
    const float* Vk = (const float*)d_in[4];
    const float* Vv = (const float*)d_in[5];
    const float* bq = (const float*)d_in[6];
    const float* bk = (const float*)d_in[7];
    const float* bv = (const float*)d_in[8];
    const int* amask = (const int*)d_in[9];
    const int* pos   = (const int*)d_in[10];

    dim3 pg(DD / 64, (BB * MM) / 64, 3);     // 16 x 64 x 3
    proj_kernel<<<pg, 256>>>(Pq, Pk, Pv, Vq, Vk, Vv, bq, bk, bv, pos);

    dim3 ag(BB * HH, MM / 128);              // 32 x 16
    attn_kernel<<<ag, 128>>>(amask, (float*)d_out);
}

// round 3
// speedup vs baseline: 3.8755x; 3.8755x over previous
#include <cuda_runtime.h>
#include <cstdint>

#define BB 2
#define MM 2048
#define RR 256
#define HH 16
#define DHH 64
#define DD (HH*DHH)

// Scratch: q,k,v in (b,h,m,dh) layout, fp32 values already rounded to tf32.
__device__ float g_q[BB*HH*MM*DHH];
__device__ float g_k[BB*HH*MM*DHH];
__device__ float g_v[BB*HH*MM*DHH];

// ---------------- packed f32x2 helpers (projection GEMM) ----------------
__device__ __forceinline__ uint64_t pack2(float x) {
    uint64_t r; uint32_t u = __float_as_uint(x);
    asm("mov.b64 %0, {%1, %1};" : "=l"(r) : "r"(u));
    return r;
}
__device__ __forceinline__ uint64_t fma2(uint64_t a, uint64_t b, uint64_t c) {
    uint64_t d;
    asm("fma.rn.f32x2 %0, %1, %2, %3;" : "=l"(d) : "l"(a), "l"(b), "l"(c));
    return d;
}
__device__ __forceinline__ float f2lo(uint64_t v) { return __uint_as_float((uint32_t)v); }
__device__ __forceinline__ float f2hi(uint64_t v) { return __uint_as_float((uint32_t)(v >> 32)); }

// ---------------- misc helpers ----------------
__device__ __forceinline__ float tf32r(float x) {            // round-to-nearest tf32
    uint32_t u;
    asm("cvt.rna.tf32.f32 %0, %1;" : "=r"(u) : "f"(x));
    return __uint_as_float(u);
}
__device__ __forceinline__ uint32_t smem_u32(const void* p) {
    uint32_t a;
    asm("{ .reg .u64 t; cvta.to.shared.u64 t, %1; cvt.u32.u64 %0, t; }" : "=r"(a) : "l"(p));
    return a;
}
__device__ __forceinline__ void cp16(uint32_t dst, const void* src) {
    asm volatile("cp.async.cg.shared.global [%0], [%1], 16;" :: "r"(dst), "l"(src) : "memory");
}
__device__ __forceinline__ void cp_commit() { asm volatile("cp.async.commit_group;" ::: "memory"); }
template <int N>
__device__ __forceinline__ void cp_wait() { asm volatile("cp.async.wait_group %0;" :: "n"(N) : "memory"); }
__device__ __forceinline__ float ex2f(float x) {
    float r;
    asm("ex2.approx.ftz.f32 %0, %1;" : "=f"(r) : "f"(x));
    return r;
}
// m16n8k8 tf32 warp MMA (sm_80+, legal on compute_103)
__device__ __forceinline__ void mma8(float* c, const uint32_t* a, uint32_t b0, uint32_t b1) {
    asm volatile("mma.sync.aligned.m16n8k8.row.col.f32.tf32.tf32.f32 "
        "{%0,%1,%2,%3}, {%4,%5,%6,%7}, {%8,%9}, {%0,%1,%2,%3};"
        : "+f"(c[0]), "+f"(c[1]), "+f"(c[2]), "+f"(c[3])
        : "r"(a[0]), "r"(a[1]), "r"(a[2]), "r"(a[3]), "r"(b0), "r"(b1));
}
__device__ __forceinline__ uint32_t fbits(float x) { return __float_as_uint(x); }

// ---------------------------------------------------------------------------
// Projection: X = P(4096x256) @ V(256x1024) + bias, RoPE for q/k, outputs
// rounded to tf32 so the attention mainloop can feed raw bits to mma.sync.
// ---------------------------------------------------------------------------
__global__ __launch_bounds__(256) void proj_kernel(
    const float* __restrict__ Pq, const float* __restrict__ Pk, const float* __restrict__ Pv,
    const float* __restrict__ Vq, const float* __restrict__ Vk, const float* __restrict__ Vv,
    const float* __restrict__ bq, const float* __restrict__ bk, const float* __restrict__ bv,
    const int* __restrict__ pos_ids)
{
    const int z = blockIdx.z;
    const float* P    = (z == 0) ? Pq : (z == 1) ? Pk : Pv;
    const float* V    = (z == 0) ? Vq : (z == 1) ? Vk : Vv;
    const float* bias = (z == 0) ? bq : (z == 1) ? bk : bv;
    float* dst        = (z == 0) ? g_q : (z == 1) ? g_k : g_v;

    __shared__ float As[32][65];
    __shared__ float Bs[32][64];

    const int tid = threadIdx.x;
    const int tx = tid & 15, ty = tid >> 4;
    const int n0 = blockIdx.x * 64;           // head = blockIdx.x
    const int m0 = blockIdx.y * 64;           // row base within B*M

    uint64_t c2[4][2];
    #pragma unroll
    for (int i = 0; i < 4; i++) { c2[i][0] = 0ull; c2[i][1] = 0ull; }

    for (int k0 = 0; k0 < RR; k0 += 32) {
        #pragma unroll
        for (int e = 0; e < 8; e++) {
            int idx = e * 256 + tid;
            int r = idx >> 5, c = idx & 31;
            As[c][r] = P[(size_t)(m0 + r) * RR + k0 + c];
        }
        #pragma unroll
        for (int e = 0; e < 8; e++) {
            int idx = e * 256 + tid;
            int kk = idx >> 6, nn = idx & 63;
            Bs[kk][nn] = V[(size_t)(k0 + kk) * DD + n0 + nn];
        }
        __syncthreads();
        #pragma unroll
        for (int k = 0; k < 32; k++) {
            const uint64_t* brow = (const uint64_t*)&Bs[k][0];
            uint64_t b20 = brow[tx];
            uint64_t b21 = brow[tx + 16];
            #pragma unroll
            for (int i = 0; i < 4; i++) {
                uint64_t aa = pack2(As[k][ty * 4 + i]);
                c2[i][0] = fma2(aa, b20, c2[i][0]);
                c2[i][1] = fma2(aa, b21, c2[i][1]);
            }
        }
        __syncthreads();
    }

    const int col0 = 2 * tx;
    const float bi0 = bias[n0 + col0];
    const float bi1 = bias[n0 + col0 + 1];
    const float bi2 = bias[n0 + col0 + 32];
    const float bi3 = bias[n0 + col0 + 33];
    const float Lc = 0.41524101186092033f;   // log2(10000)/32
    const float inva = exp2f(-(float)col0 * Lc);
    const float invb = exp2f(-(float)(col0 + 1) * Lc);
    const int h = blockIdx.x;

    #pragma unroll
    for (int i = 0; i < 4; i++) {
        int row = m0 + ty * 4 + i;           // 0..4095
        int b = row >> 11;
        int m = row & (MM - 1);
        float x0a = f2lo(c2[i][0]) + bi0;
        float x0b = f2hi(c2[i][0]) + bi1;
        float x1a = f2lo(c2[i][1]) + bi2;
        float x1b = f2hi(c2[i][1]) + bi3;
        float* o = dst + ((size_t)(b * HH + h) * MM + m) * DHH;
        if (z == 2) {
            o[col0]      = tf32r(x0a);
            o[col0 + 1]  = tf32r(x0b);
            o[col0 + 32] = tf32r(x1a);
            o[col0 + 33] = tf32r(x1b);
        } else {
            float pos = (float)pos_ids[row];
            float sa, ca, sb, cb;
            sincosf(pos * inva, &sa, &ca);
            sincosf(pos * invb, &sb, &cb);
            o[col0]      = tf32r(x0a * ca - x1a * sa);
            o[col0 + 1]  = tf32r(x0b * cb - x1b * sb);
            o[col0 + 32] = tf32r(x0a * sa + x1a * ca);
            o[col0 + 33] = tf32r(x0b * sb + x1b * cb);
        }
    }
}

// ---------------------------------------------------------------------------
// Attention: warp-level tf32 mma.sync flash attention, fixed-offset softmax.
// CTA = 256 query rows x (b,h); 8 warps x 32 rows each; keys in 64-blocks.
// Smem (bytes):
//   Q  : 256 rows x pitch 68 floats = 69632
//   P  : 256 rows x pitch 72 floats = 73728
//   Kt : 2 x (64 dh x pitch 72)     = 36864   (K transposed: Kt[dh][key])
//   V  : 2 x (64 key x pitch 72)    = 36864   (natural: V[key][dh])
//   msk: 2 x 64 ints                = 512
// ---------------------------------------------------------------------------
#define Q_OFF   0
#define P_OFF   69632
#define KT_OFF  143360
#define V_OFF   180224
#define MSK_OFF 217088
#define SMEM_TOTAL 217600
#define KV_STRIDE 18432

__global__ __launch_bounds__(256, 1) void attn_kernel(const int* __restrict__ amask,
                                                      float* __restrict__ out)
{
    extern __shared__ char smem[];
    float* Qs = (float*)(smem + Q_OFF);
    float* Ps = (float*)(smem + P_OFF);
    const uint32_t sb = smem_u32(smem);

    const int tid = threadIdx.x;
    const int w = tid >> 5, lane = tid & 31;
    const int r = lane & 3, q = lane >> 2;
    const int bh = blockIdx.x;
    const int b = bh >> 4;
    const int m0 = blockIdx.y * 256;

    const float* qg = g_q + ((size_t)bh * MM + m0) * DHH;
    const float* kg = g_k + (size_t)bh * MM * DHH;
    const float* vg = g_v + (size_t)bh * MM * DHH;

    // ---- prologue: Q tile, V block0, mask0 via cp.async; K block0 staged ----
    #pragma unroll
    for (int e = 0; e < 16; e++) {
        int c = e * 256 + tid;
        int row = c >> 4, f4 = c & 15;
        cp16(sb + Q_OFF + row * 272 + f4 * 16, qg + row * 64 + f4 * 4);
    }
    #pragma unroll
    for (int e = 0; e < 4; e++) {
        int c = e * 256 + tid;
        int key = c >> 4, f4 = c & 15;
        cp16(sb + V_OFF + key * 288 + f4 * 16, vg + key * 64 + f4 * 4);
    }
    if (tid < 16) cp16(sb + MSK_OFF + tid * 16, amask + (size_t)b * MM + tid * 4);
    cp_commit();

    const int keyk = tid & 63, chunk = tid >> 6;   // K-staging assignment
    {
        float4 kr[4];
        #pragma unroll
        for (int e = 0; e < 4; e++)
            kr[e] = *(const float4*)(kg + (size_t)keyk * 64 + chunk * 16 + e * 4);
        float* kt = (float*)(smem + KT_OFF) + keyk;
        #pragma unroll
        for (int e = 0; e < 4; e++) {
            int d0 = chunk * 16 + e * 4;
            kt[(d0 + 0) * 72] = kr[e].x;
            kt[(d0 + 1) * 72] = kr[e].y;
            kt[(d0 + 2) * 72] = kr[e].z;
            kt[(d0 + 3) * 72] = kr[e].w;
        }
    }
    cp_wait<0>();
    __syncthreads();

    // ---- persistent accumulators ----
    float oc[2][8][4];
    #pragma unroll
    for (int g = 0; g < 2; g++)
        #pragma unroll
        for (int j = 0; j < 8; j++)
            #pragma unroll
            for (int c = 0; c < 4; c++) oc[g][j][c] = 0.0f;
    float ls[2][2] = {{0.f, 0.f}, {0.f, 0.f}};   // [group][lo/hi row]

    const float C1 = 0.18033688011112042f;   // (1/8)*log2(e)
    const float C2 = 43.28085122666891f;     // 30*log2(e)
    const int row0b = w * 32 + q;

    for (int i = 0; i < 32; i++) {
        const int buf = i & 1, nb = buf ^ 1;
        const bool pf = (i < 31);
        float4 kr[4];
        if (pf) {
            int n1 = (i + 1) * 64;
            #pragma unroll
            for (int e = 0; e < 4; e++) {
                int c = e * 256 + tid;
                int key = c >> 4, f4 = c & 15;
                cp16(sb + V_OFF + nb * KV_STRIDE + key * 288 + f4 * 16,
                     vg + (size_t)(n1 + key) * 64 + f4 * 4);
            }
            if (tid < 16) cp16(sb + MSK_OFF + nb * 256 + tid * 16,
                               amask + (size_t)b * MM + n1 + tid * 4);
            cp_commit();
            #pragma unroll
            for (int e = 0; e < 4; e++)
                kr[e] = *(const float4*)(kg + (size_t)(n1 + keyk) * 64 + chunk * 16 + e * 4);
        }

        // ---- S = Q(32 rows) x K^T(64) ----
        const float* kt = (const float*)(smem + KT_OFF + buf * KV_STRIDE);
        float sc[2][8][4];
        #pragma unroll
        for (int g = 0; g < 2; g++)
            #pragma unroll
            for (int j = 0; j < 8; j++)
                #pragma unroll
                for (int c = 0; c < 4; c++) sc[g][j][c] = 0.0f;

        #pragma unroll
        for (int s = 0; s < 8; s++) {
            uint32_t a[2][4];
            #pragma unroll
            for (int g = 0; g < 2; g++) {
                int row = row0b + g * 16;
                a[g][0] = fbits(Qs[row * 68 + 8 * s + r]);
                a[g][1] = fbits(Qs[(row + 8) * 68 + 8 * s + r]);
                a[g][2] = fbits(Qs[row * 68 + 8 * s + r + 4]);
                a[g][3] = fbits(Qs[(row + 8) * 68 + 8 * s + r + 4]);
            }
            #pragma unroll
            for (int j = 0; j < 8; j++) {
                uint32_t b0 = fbits(kt[(8 * s + r) * 72 + 8 * j + q]);
                uint32_t b1 = fbits(kt[(8 * s + 4 + r) * 72 + 8 * j + q]);
                mma8(sc[0][j], a[0], b0, b1);
                mma8(sc[1][j], a[1], b0, b1);
            }
        }

        // ---- softmax epilogue: p = exp(s/8 - 30), write P ----
        const int2* mk = (const int2*)(smem + MSK_OFF + buf * 256);
        #pragma unroll
        for (int j = 0; j < 8; j++) {
            int2 mv = mk[j * 4 + r];
            #pragma unroll
            for (int g = 0; g < 2; g++) {
                float p0 = ex2f(fmaf(sc[g][j][0], C1, -C2)); if (!mv.x) p0 = 0.f;
                float p1 = ex2f(fmaf(sc[g][j][1], C1, -C2)); if (!mv.y) p1 = 0.f;
                float p2 = ex2f(fmaf(sc[g][j][2], C1, -C2)); if (!mv.x) p2 = 0.f;
                float p3 = ex2f(fmaf(sc[g][j][3], C1, -C2)); if (!mv.y) p3 = 0.f;
                ls[g][0] += p0 + p1;
                ls[g][1] += p2 + p3;
                int row = row0b + g * 16;
                *(float2*)&Ps[row * 72 + 8 * j + 2 * r]       = make_float2(tf32r(p0), tf32r(p1));
                *(float2*)&Ps[(row + 8) * 72 + 8 * j + 2 * r] = make_float2(tf32r(p2), tf32r(p3));
            }
        }
        __syncthreads();

        // ---- O += P x V ----
        const float* vt = (const float*)(smem + V_OFF + buf * KV_STRIDE);
        #pragma unroll
        for (int s = 0; s < 8; s++) {
            uint32_t a[2][4];
            #pragma unroll
            for (int g = 0; g < 2; g++) {
                int row = row0b + g * 16;
                a[g][0] = fbits(Ps[row * 72 + 8 * s + r]);
                a[g][1] = fbits(Ps[(row + 8) * 72 + 8 * s + r]);
                a[g][2] = fbits(Ps[row * 72 + 8 * s + r + 4]);
                a[g][3] = fbits(Ps[(row + 8) * 72 + 8 * s + r + 4]);
            }
            #pragma unroll
            for (int j = 0; j < 8; j++) {
                uint32_t b0 = fbits(vt[(8 * s + r) * 72 + 8 * j + q]);
                uint32_t b1 = fbits(vt[(8 * s + 4 + r) * 72 + 8 * j + q]);
                mma8(oc[0][j], a[0], b0, b1);
                mma8(oc[1][j], a[1], b0, b1);
            }
        }

        if (pf) {
            float* kt2 = (float*)(smem + KT_OFF + nb * KV_STRIDE) + keyk;
            #pragma unroll
            for (int e = 0; e < 4; e++) {
                int d0 = chunk * 16 + e * 4;
                kt2[(d0 + 0) * 72] = kr[e].x;
                kt2[(d0 + 1) * 72] = kr[e].y;
                kt2[(d0 + 2) * 72] = kr[e].z;
                kt2[(d0 + 3) * 72] = kr[e].w;
            }
        }
        cp_wait<0>();
        __syncthreads();
    }

    // ---- finalize: reduce l over the 4 lanes of each row quad, normalize ----
    #pragma unroll
    for (int g = 0; g < 2; g++) {
        float l0 = ls[g][0];
        l0 += __shfl_xor_sync(0xffffffffu, l0, 1);
        l0 += __shfl_xor_sync(0xffffffffu, l0, 2);
        float l1 = ls[g][1];
        l1 += __shfl_xor_sync(0xffffffffu, l1, 1);
        l1 += __shfl_xor_sync(0xffffffffu, l1, 2);
        float i0 = (l0 > 0.f) ? (1.0f / l0) : 0.f;
        float i1 = (l1 > 0.f) ? (1.0f / l1) : 0.f;
        int row = row0b + g * 16;
        float* o0 = out + ((size_t)bh * MM + m0 + row) * DHH;
        float* o1 = out + ((size_t)bh * MM + m0 + row + 8) * DHH;
        #pragma unroll
        for (int j = 0; j < 8; j++) {
            *(float2*)(o0 + 8 * j + 2 * r) = make_float2(oc[g][j][0] * i0, oc[g][j][1] * i0);
            *(float2*)(o1 + 8 * j + 2 * r) = make_float2(oc[g][j][2] * i1, oc[g][j][3] * i1);
        }
    }
}

extern "C" void kernel_launch(void* const* d_in, const int* in_sizes, int n_in,
                              void* d_out, int out_size) {
    const float* Pq = (const float*)d_in[0];
    const float* Pk = (const float*)d_in[1];
    const float* Pv = (const float*)d_in[2];
    const float* Vq = (const float*)d_in[3];
    const float* Vk = (const float*)d_in[4];
    const float* Vv = (const float*)d_in[5];
    const float* bq = (const float*)d_in[6];
    const float* bk = (const float*)d_in[7];
    const float* bv = (const float*)d_in[8];
    const int* amask = (const int*)d_in[9];
    const int* pos   = (const int*)d_in[10];

    static int smem_set = 0;
    if (!smem_set) {
        cudaFuncSetAttribute(attn_kernel, cudaFuncAttributeMaxDynamicSharedMemorySize, SMEM_TOTAL);
        smem_set = 1;
    }

    dim3 pg(DD / 64, (BB * MM) / 64, 3);     // 16 x 64 x 3
    proj_kernel<<<pg, 256>>>(Pq, Pk, Pv, Vq, Vk, Vv, bq, bk, bv, pos);

    dim3 ag(BB * HH, MM / 256);              // 32 x 8
    attn_kernel<<<ag, 256, SMEM_TOTAL>>>(amask, (float*)d_out);
}

// round 4
// speedup vs baseline: 6.0747x; 1.5675x over previous
#include <cuda_runtime.h>
#include <cuda_bf16.h>
#include <cstdint>

#define BB 2
#define MM 2048
#define RR 256
#define HH 16
#define DHH 64
#define DD (HH*DHH)

// Scratch (bf16): q,k in (b,h,m,dh); v TRANSPOSED in (b,h,dh,m).
__device__ __align__(128) __nv_bfloat16 g_q[BB*HH*MM*DHH];
__device__ __align__(128) __nv_bfloat16 g_k[BB*HH*MM*DHH];
__device__ __align__(128) __nv_bfloat16 g_v[BB*HH*MM*DHH];

// ---------------- packed f32x2 helpers (projection GEMM) ----------------
__device__ __forceinline__ uint64_t pack2(float x) {
    uint64_t r; uint32_t u = __float_as_uint(x);
    asm("mov.b64 %0, {%1, %1};" : "=l"(r) : "r"(u));
    return r;
}
__device__ __forceinline__ uint64_t fma2(uint64_t a, uint64_t b, uint64_t c) {
    uint64_t d;
    asm("fma.rn.f32x2 %0, %1, %2, %3;" : "=l"(d) : "l"(a), "l"(b), "l"(c));
    return d;
}
__device__ __forceinline__ float f2lo(uint64_t v) { return __uint_as_float((uint32_t)v); }
__device__ __forceinline__ float f2hi(uint64_t v) { return __uint_as_float((uint32_t)(v >> 32)); }

// ---------------- misc helpers ----------------
__device__ __forceinline__ uint32_t smem_u32(const void* p) {
    uint32_t a;
    asm("{ .reg .u64 t; cvta.to.shared.u64 t, %1; cvt.u32.u64 %0, t; }" : "=r"(a) : "l"(p));
    return a;
}
__device__ __forceinline__ void cp16(uint32_t dst, const void* src) {
    asm volatile("cp.async.cg.shared.global [%0], [%1], 16;" :: "r"(dst), "l"(src) : "memory");
}
__device__ __forceinline__ void cp_commit() { asm volatile("cp.async.commit_group;" ::: "memory"); }
template <int N>
__device__ __forceinline__ void cp_wait() { asm volatile("cp.async.wait_group %0;" :: "n"(N) : "memory"); }
__device__ __forceinline__ float ex2f(float x) {
    float r;
    asm("ex2.approx.ftz.f32 %0, %1;" : "=f"(r) : "f"(x));
    return r;
}
__device__ __forceinline__ uint32_t bf2(float lo, float hi) {
    __nv_bfloat162 t = __floats2bfloat162_rn(lo, hi);
    return *(uint32_t*)&t;
}
// m16n8k16 bf16 warp MMA (sm_80+, legal on compute_103)
__device__ __forceinline__ void mmab(float* c, const uint32_t* a, uint32_t b0, uint32_t b1) {
    asm volatile("mma.sync.aligned.m16n8k16.row.col.f32.bf16.bf16.f32 "
        "{%0,%1,%2,%3}, {%4,%5,%6,%7}, {%8,%9}, {%0,%1,%2,%3};"
        : "+f"(c[0]), "+f"(c[1]), "+f"(c[2]), "+f"(c[3])
        : "r"(a[0]), "r"(a[1]), "r"(a[2]), "r"(a[3]), "r"(b0), "r"(b1));
}

// ---------------------------------------------------------------------------
// Projection: X = P(4096x256) @ V(256x1024) + bias, RoPE for q/k; bf16 out.
// v written transposed (b,h,dh,m) via smem stage.
// ---------------------------------------------------------------------------
__global__ __launch_bounds__(256) void proj_kernel(
    const float* __restrict__ Pq, const float* __restrict__ Pk, const float* __restrict__ Pv,
    const float* __restrict__ Vq, const float* __restrict__ Vk, const float* __restrict__ Vv,
    const float* __restrict__ bq, const float* __restrict__ bk, const float* __restrict__ bv,
    const int* __restrict__ pos_ids)
{
    const int z = blockIdx.z;
    const float* P    = (z == 0) ? Pq : (z == 1) ? Pk : Pv;
    const float* V    = (z == 0) ? Vq : (z == 1) ? Vk : Vv;
    const float* bias = (z == 0) ? bq : (z == 1) ? bk : bv;
    __nv_bfloat16* dst = (z == 0) ? g_q : (z == 1) ? g_k : g_v;

    __shared__ float As[32][65];
    __shared__ float Bs[32][64];
    __shared__ float stage[64][65];

    const int tid = threadIdx.x;
    const int tx = tid & 15, ty = tid >> 4;
    const int n0 = blockIdx.x * 64;           // head = blockIdx.x
    const int m0 = blockIdx.y * 64;

    uint64_t c2[4][2];
    #pragma unroll
    for (int i = 0; i < 4; i++) { c2[i][0] = 0ull; c2[i][1] = 0ull; }

    for (int k0 = 0; k0 < RR; k0 += 32) {
        #pragma unroll
        for (int e = 0; e < 8; e++) {
            int idx = e * 256 + tid;
            int r = idx >> 5, c = idx & 31;
            As[c][r] = P[(size_t)(m0 + r) * RR + k0 + c];
        }
        #pragma unroll
        for (int e = 0; e < 8; e++) {
            int idx = e * 256 + tid;
            int kk = idx >> 6, nn = idx & 63;
            Bs[kk][nn] = V[(size_t)(k0 + kk) * DD + n0 + nn];
        }
        __syncthreads();
        #pragma unroll
        for (int k = 0; k < 32; k++) {
            const uint64_t* brow = (const uint64_t*)&Bs[k][0];
            uint64_t b20 = brow[tx];
            uint64_t b21 = brow[tx + 16];
            #pragma unroll
            for (int i = 0; i < 4; i++) {
                uint64_t aa = pack2(As[k][ty * 4 + i]);
                c2[i][0] = fma2(aa, b20, c2[i][0]);
                c2[i][1] = fma2(aa, b21, c2[i][1]);
            }
        }
        __syncthreads();
    }

    const int col0 = 2 * tx;
    const float bi0 = bias[n0 + col0];
    const float bi1 = bias[n0 + col0 + 1];
    const float bi2 = bias[n0 + col0 + 32];
    const float bi3 = bias[n0 + col0 + 33];
    const int h = blockIdx.x;
    const int b = m0 >> 11;
    const int mloc = m0 & (MM - 1);

    if (z == 2) {
        #pragma unroll
        for (int i = 0; i < 4; i++) {
            int r = ty * 4 + i;
            stage[r][col0]      = f2lo(c2[i][0]) + bi0;
            stage[r][col0 + 1]  = f2hi(c2[i][0]) + bi1;
            stage[r][col0 + 32] = f2lo(c2[i][1]) + bi2;
            stage[r][col0 + 33] = f2hi(c2[i][1]) + bi3;
        }
        __syncthreads();
        // transposed bf16 store: g_v[(b,h,d,m)]
        int c = tid >> 2;
        int r0 = (tid & 3) * 16;
        __nv_bfloat16* o = g_v + ((size_t)(b * HH + h) * DHH + c) * MM + mloc + r0;
        #pragma unroll
        for (int half = 0; half < 2; half++) {
            int rb = r0 + half * 8;
            uint4 w;
            w.x = bf2(stage[rb][c],     stage[rb + 1][c]);
            w.y = bf2(stage[rb + 2][c], stage[rb + 3][c]);
            w.z = bf2(stage[rb + 4][c], stage[rb + 5][c]);
            w.w = bf2(stage[rb + 6][c], stage[rb + 7][c]);
            *(uint4*)(o + half * 8) = w;
        }
    } else {
        const float Lc = 0.41524101186092033f;   // log2(10000)/32
        const float inva = exp2f(-(float)col0 * Lc);
        const float invb = exp2f(-(float)(col0 + 1) * Lc);
        #pragma unroll
        for (int i = 0; i < 4; i++) {
            int row = m0 + ty * 4 + i;
            int m = row & (MM - 1);
            float x0a = f2lo(c2[i][0]) + bi0;
            float x0b = f2hi(c2[i][0]) + bi1;
            float x1a = f2lo(c2[i][1]) + bi2;
            float x1b = f2hi(c2[i][1]) + bi3;
            __nv_bfloat16* o = dst + ((size_t)(b * HH + h) * MM + m) * DHH;
            float pos = (float)pos_ids[row];
            float sa, ca, sb, cb;
            sincosf(pos * inva, &sa, &ca);
            sincosf(pos * invb, &sb, &cb);
            *(__nv_bfloat162*)&o[col0] =
                __floats2bfloat162_rn(x0a * ca - x1a * sa, x0b * cb - x1b * sb);
            *(__nv_bfloat162*)&o[col0 + 32] =
                __floats2bfloat162_rn(x0a * sa + x1a * ca, x0b * sb + x1b * cb);
        }
    }
}

// ---------------------------------------------------------------------------
// Attention: bf16 m16n8k16 mma.sync flash attention, fixed-offset softmax,
// register-resident P (C-frag -> A-frag conversion). CTA = 256 rows, 8 warps.
// Smem: Q 256x(64+8)bf16 = 36864 | K 2x 64x72 bf16 = 18432 |
//       Vt 2x 64x72 bf16 = 18432 | mask 2x 64 int = 512    -> 74240 B
// ---------------------------------------------------------------------------
#define Q_OFF   0
#define K_OFF   36864
#define V_OFF   55296
#define MSK_OFF 73728
#define SMEM_TOTAL 74240
#define KV_STRIDE 9216
#define PITCHW 36   // 72 bf16 = 36 uint32 words per row

__global__ __launch_bounds__(256, 1) void attn_kernel(const int* __restrict__ amask,
                                                      float* __restrict__ out)
{
    extern __shared__ char smem[];
    const uint32_t sb = smem_u32(smem);
    const uint32_t* Qw = (const uint32_t*)(smem + Q_OFF);

    const int tid = threadIdx.x;
    const int w = tid >> 5, lane = tid & 31;
    const int g = lane >> 2, tg = lane & 3;
    const int bh = blockIdx.x;
    const int b = bh >> 4;
    const int m0 = blockIdx.y * 256;

    const __nv_bfloat16* qg = g_q + ((size_t)bh * MM + m0) * DHH;
    const __nv_bfloat16* kg = g_k + (size_t)bh * MM * DHH;
    const __nv_bfloat16* vg = g_v + (size_t)bh * DHH * MM;

    // ---- prologue: Q (256x64), K block0, Vt block0, mask0 ----
    #pragma unroll
    for (int e = 0; e < 8; e++) {
        int c = e * 256 + tid;
        int row = c >> 3, f = c & 7;
        cp16(sb + Q_OFF + row * 144 + f * 16, qg + row * 64 + f * 8);
    }
    #pragma unroll
    for (int e = 0; e < 2; e++) {
        int c = e * 256 + tid;
        int row = c >> 3, f = c & 7;
        cp16(sb + K_OFF + row * 144 + f * 16, kg + (size_t)row * 64 + f * 8);
        cp16(sb + V_OFF + row * 144 + f * 16, vg + (size_t)row * MM + f * 8);
    }
    if (tid < 16) cp16(sb + MSK_OFF + tid * 16, amask + (size_t)b * MM + tid * 4);
    cp_commit();
    cp_wait<0>();
    __syncthreads();

    // ---- persistent accumulators ----
    float oc[2][8][4];
    #pragma unroll
    for (int gi = 0; gi < 2; gi++)
        #pragma unroll
        for (int j = 0; j < 8; j++)
            #pragma unroll
            for (int c = 0; c < 4; c++) oc[gi][j][c] = 0.0f;
    float ls[2][2] = {{0.f, 0.f}, {0.f, 0.f}};

    const float C1 = 0.18033688011112042f;   // (1/8)*log2(e)
    const float C2 = 43.28085122666891f;     // 30*log2(e)
    const int row0 = w * 32;

    for (int i = 0; i < 32; i++) {
        const int buf = i & 1, nb = buf ^ 1;

        // prefetch next block into other buffer
        if (i < 31) {
            int n1 = (i + 1) * 64;
            #pragma unroll
            for (int e = 0; e < 2; e++) {
                int c = e * 256 + tid;
                int row = c >> 3, f = c & 7;
                cp16(sb + K_OFF + nb * KV_STRIDE + row * 144 + f * 16,
                     kg + (size_t)(n1 + row) * 64 + f * 8);
                cp16(sb + V_OFF + nb * KV_STRIDE + row * 144 + f * 16,
                     vg + (size_t)row * MM + n1 + f * 8);
            }
            if (tid < 16) cp16(sb + MSK_OFF + nb * 256 + tid * 16,
                               amask + (size_t)b * MM + n1 + tid * 4);
            cp_commit();
        }

        const uint32_t* Kw = (const uint32_t*)(smem + K_OFF + buf * KV_STRIDE);
        const uint32_t* Vw = (const uint32_t*)(smem + V_OFF + buf * KV_STRIDE);

        // ---- S = Q(32 rows) x K^T(64 keys) ----
        float sc[2][8][4];
        #pragma unroll
        for (int gi = 0; gi < 2; gi++)
            #pragma unroll
            for (int j = 0; j < 8; j++)
                #pragma unroll
                for (int c = 0; c < 4; c++) sc[gi][j][c] = 0.0f;

        #pragma unroll
        for (int s = 0; s < 4; s++) {
            uint32_t a[2][4];
            #pragma unroll
            for (int gi = 0; gi < 2; gi++) {
                int ra = row0 + gi * 16 + g;
                a[gi][0] = Qw[ra * PITCHW + 8 * s + tg];
                a[gi][1] = Qw[(ra + 8) * PITCHW + 8 * s + tg];
                a[gi][2] = Qw[ra * PITCHW + 8 * s + tg + 4];
                a[gi][3] = Qw[(ra + 8) * PITCHW + 8 * s + tg + 4];
            }
            #pragma unroll
            for (int j = 0; j < 8; j++) {
                uint32_t b0 = Kw[(8 * j + g) * PITCHW + 8 * s + tg];
                uint32_t b1 = Kw[(8 * j + g) * PITCHW + 8 * s + tg + 4];
                mmab(sc[0][j], a[0], b0, b1);
                mmab(sc[1][j], a[1], b0, b1);
            }
        }

        // ---- softmax: p = exp(s/8 - 30); pack C-frags into A-frags ----
        const int* msk = (const int*)(smem + MSK_OFF + buf * 256);
        uint32_t pa[2][4][4];
        #pragma unroll
        for (int j = 0; j < 8; j++) {
            int2 mv = *(const int2*)&msk[8 * j + 2 * tg];
            #pragma unroll
            for (int gi = 0; gi < 2; gi++) {
                float p0 = ex2f(fmaf(sc[gi][j][0], C1, -C2)); if (!mv.x) p0 = 0.f;
                float p1 = ex2f(fmaf(sc[gi][j][1], C1, -C2)); if (!mv.y) p1 = 0.f;
                float p2 = ex2f(fmaf(sc[gi][j][2], C1, -C2)); if (!mv.x) p2 = 0.f;
                float p3 = ex2f(fmaf(sc[gi][j][3], C1, -C2)); if (!mv.y) p3 = 0.f;
                ls[gi][0] += p0 + p1;
                ls[gi][1] += p2 + p3;
                int s = j >> 1;
                if ((j & 1) == 0) {
                    pa[gi][s][0] = bf2(p0, p1);
                    pa[gi][s][1] = bf2(p2, p3);
                } else {
                    pa[gi][s][2] = bf2(p0, p1);
                    pa[gi][s][3] = bf2(p2, p3);
                }
            }
        }

        // ---- O += P x V (A from registers, B from transposed V) ----
        #pragma unroll
        for (int s = 0; s < 4; s++) {
            #pragma unroll
            for (int j = 0; j < 8; j++) {
                uint32_t b0 = Vw[(8 * j + g) * PITCHW + 8 * s + tg];
                uint32_t b1 = Vw[(8 * j + g) * PITCHW + 8 * s + tg + 4];
                mmab(oc[0][j], pa[0][s], b0, b1);
                mmab(oc[1][j], pa[1][s], b0, b1);
            }
        }

        cp_wait<0>();
        __syncthreads();
    }

    // ---- finalize: reduce l across the quad, normalize, store ----
    #pragma unroll
    for (int gi = 0; gi < 2; gi++) {
        float l0 = ls[gi][0];
        l0 += __shfl_xor_sync(0xffffffffu, l0, 1);
        l0 += __shfl_xor_sync(0xffffffffu, l0, 2);
        float l1 = ls[gi][1];
        l1 += __shfl_xor_sync(0xffffffffu, l1, 1);
        l1 += __shfl_xor_sync(0xffffffffu, l1, 2);
        float i0 = (l0 > 0.f) ? (1.0f / l0) : 0.f;
        float i1 = (l1 > 0.f) ? (1.0f / l1) : 0.f;
        int row = row0 + gi * 16 + g;
        float* o0 = out + ((size_t)bh * MM + m0 + row) * DHH;
        float* o1 = out + ((size_t)bh * MM + m0 + row + 8) * DHH;
        #pragma unroll
        for (int j = 0; j < 8; j++) {
            *(float2*)(o0 + 8 * j + 2 * tg) = make_float2(oc[gi][j][0] * i0, oc[gi][j][1] * i0);
            *(float2*)(o1 + 8 * j + 2 * tg) = make_float2(oc[gi][j][2] * i1, oc[gi][j][3] * i1);
        }
    }
}

extern "C" void kernel_launch(void* const* d_in, const int* in_sizes, int n_in,
                              void* d_out, int out_size) {
    const float* Pq = (const float*)d_in[0];
    const float* Pk = (const float*)d_in[1];
    const float* Pv = (const float*)d_in[2];
    const float* Vq = (const float*)d_in[3];
    const float* Vk = (const float*)d_in[4];
    const float* Vv = (const float*)d_in[5];
    const float* bq = (const float*)d_in[6];
    const float* bk = (const float*)d_in[7];
    const float* bv = (const float*)d_in[8];
    const int* amask = (const int*)d_in[9];
    const int* pos   = (const int*)d_in[10];

    static int smem_set = 0;
    if (!smem_set) {
        cudaFuncSetAttribute(attn_kernel, cudaFuncAttributeMaxDynamicSharedMemorySize, SMEM_TOTAL);
        smem_set = 1;
    }

    dim3 pg(DD / 64, (BB * MM) / 64, 3);     // 16 x 64 x 3
    proj_kernel<<<pg, 256>>>(Pq, Pk, Pv, Vq, Vk, Vv, bq, bk, bv, pos);

    dim3 ag(BB * HH, MM / 256);              // 32 x 8
    attn_kernel<<<ag, 256, SMEM_TOTAL>>>(amask, (float*)d_out);
}

// round 5
// speedup vs baseline: 10.1943x; 1.6782x over previous
#include <cuda_runtime.h>
#include <cuda_bf16.h>
#include <cstdint>

#define BB 2
#define MM 2048
#define RR 256
#define HH 16
#define DHH 64
#define DD (HH*DHH)

// Scratch (bf16): q,k in (b,h,m,dh); v TRANSPOSED in (b,h,dh,m).
__device__ __align__(128) __nv_bfloat16 g_q[BB*HH*MM*DHH];
__device__ __align__(128) __nv_bfloat16 g_k[BB*HH*MM*DHH];
__device__ __align__(128) __nv_bfloat16 g_v[BB*HH*MM*DHH];
// RoPE table: per (b*M+m) row, 32 cos then 32 sin.
__device__ __align__(128) float g_cs[BB*MM*64];

// ---------------- misc helpers ----------------
__device__ __forceinline__ uint32_t smem_u32(const void* p) {
    uint32_t a;
    asm("{ .reg .u64 t; cvta.to.shared.u64 t, %1; cvt.u32.u64 %0, t; }" : "=r"(a) : "l"(p));
    return a;
}
__device__ __forceinline__ void cp16(uint32_t dst, const void* src) {
    asm volatile("cp.async.cg.shared.global [%0], [%1], 16;" :: "r"(dst), "l"(src) : "memory");
}
__device__ __forceinline__ void cp_commit() { asm volatile("cp.async.commit_group;" ::: "memory"); }
template <int N>
__device__ __forceinline__ void cp_wait() { asm volatile("cp.async.wait_group %0;" :: "n"(N) : "memory"); }
__device__ __forceinline__ float ex2f(float x) {
    float r;
    asm("ex2.approx.ftz.f32 %0, %1;" : "=f"(r) : "f"(x));
    return r;
}
__device__ __forceinline__ uint32_t bf2(float lo, float hi) {
    __nv_bfloat162 t = __floats2bfloat162_rn(lo, hi);
    return *(uint32_t*)&t;
}
__device__ __forceinline__ uint32_t fbits(float x) { return __float_as_uint(x); }

// m16n8k16 bf16 warp MMA
__device__ __forceinline__ void mmab(float* c, const uint32_t* a, uint32_t b0, uint32_t b1) {
    asm volatile("mma.sync.aligned.m16n8k16.row.col.f32.bf16.bf16.f32 "
        "{%0,%1,%2,%3}, {%4,%5,%6,%7}, {%8,%9}, {%0,%1,%2,%3};"
        : "+f"(c[0]), "+f"(c[1]), "+f"(c[2]), "+f"(c[3])
        : "r"(a[0]), "r"(a[1]), "r"(a[2]), "r"(a[3]), "r"(b0), "r"(b1));
}
// m16n8k8 tf32 warp MMA
__device__ __forceinline__ void mma8(float* c, const uint32_t* a, uint32_t b0, uint32_t b1) {
    asm volatile("mma.sync.aligned.m16n8k8.row.col.f32.tf32.tf32.f32 "
        "{%0,%1,%2,%3}, {%4,%5,%6,%7}, {%8,%9}, {%0,%1,%2,%3};"
        : "+f"(c[0]), "+f"(c[1]), "+f"(c[2]), "+f"(c[3])
        : "r"(a[0]), "r"(a[1]), "r"(a[2]), "r"(a[3]), "r"(b0), "r"(b1));
}

// ---------------------------------------------------------------------------
// RoPE table: g_cs[row][f] = cos(pos*invfreq_f), [32+f] = sin(...)
// ---------------------------------------------------------------------------
__global__ __launch_bounds__(256) void rope_kernel(const int* __restrict__ pos_ids) {
    int idx = blockIdx.x * 256 + threadIdx.x;       // 0 .. BB*MM*32-1
    int f = idx & 31, row = idx >> 5;
    float p = (float)pos_ids[row];
    float inv = exp2f(-(float)f * 0.41524101186092033f);  // log2(10000)/32
    float s, c;
    sincosf(p * inv, &s, &c);
    g_cs[row * 64 + f] = c;
    g_cs[row * 64 + 32 + f] = s;
}

// ---------------------------------------------------------------------------
// Projection via tf32 mma.sync: X(4096x1024) = P(4096x256) @ V(256x1024) +
// bias; RoPE (table lookup) for q/k; v stored transposed (b,h,dh,m).
// CTA = 128 rows x 64 cols (one head), 4 warps x 32 rows. 8 k-chunks of 32,
// double-buffered cp.async. grid (16 heads, 32 m-tiles, 3 matrices).
// Smem: A 2x128x36f (36864) | B 2x32x68f (17408) -> 54272; stage aliases A.
// ---------------------------------------------------------------------------
#define PA_OFF 0
#define PB_OFF 36864
#define PROJ_SMEM 54272

__global__ __launch_bounds__(128) void proj_kernel(
    const float* __restrict__ Pq, const float* __restrict__ Pk, const float* __restrict__ Pv,
    const float* __restrict__ Vq, const float* __restrict__ Vk, const float* __restrict__ Vv,
    const float* __restrict__ bq, const float* __restrict__ bk, const float* __restrict__ bv)
{
    extern __shared__ char smem[];
    const uint32_t sb = smem_u32(smem);

    const int z = blockIdx.z;
    const float* P    = (z == 0) ? Pq : (z == 1) ? Pk : Pv;
    const float* V    = (z == 0) ? Vq : (z == 1) ? Vk : Vv;
    const float* bias = (z == 0) ? bq : (z == 1) ? bk : bv;
    __nv_bfloat16* dst = (z == 0) ? g_q : (z == 1) ? g_k : g_v;

    const int tid = threadIdx.x;
    const int w = tid >> 5, lane = tid & 31;
    const int g = lane >> 2, tg = lane & 3;
    const int hd = blockIdx.x;
    const int n0 = hd * 64;
    const int m0 = blockIdx.y * 128;

    // prologue: chunk 0 into buffer 0
    #pragma unroll
    for (int e = 0; e < 8; e++) {
        int c = e * 128 + tid;
        int row = c >> 3, f = c & 7;
        cp16(sb + PA_OFF + row * 144 + f * 16, P + (size_t)(m0 + row) * RR + f * 4);
    }
    #pragma unroll
    for (int e = 0; e < 4; e++) {
        int c = e * 128 + tid;
        int k = c >> 4, f = c & 15;
        cp16(sb + PB_OFF + k * 272 + f * 16, V + (size_t)k * DD + n0 + f * 4);
    }
    cp_commit();

    float acc[2][8][4];
    #pragma unroll
    for (int gi = 0; gi < 2; gi++)
        #pragma unroll
        for (int j = 0; j < 8; j++)
            #pragma unroll
            for (int c = 0; c < 4; c++) acc[gi][j][c] = 0.0f;

    for (int ch = 0; ch < 8; ch++) {
        const int buf = ch & 1, nb = buf ^ 1;
        if (ch < 7) {
            int k0 = (ch + 1) * 32;
            #pragma unroll
            for (int e = 0; e < 8; e++) {
                int c = e * 128 + tid;
                int row = c >> 3, f = c & 7;
                cp16(sb + PA_OFF + nb * 18432 + row * 144 + f * 16,
                     P + (size_t)(m0 + row) * RR + k0 + f * 4);
            }
            #pragma unroll
            for (int e = 0; e < 4; e++) {
                int c = e * 128 + tid;
                int k = c >> 4, f = c & 15;
                cp16(sb + PB_OFF + nb * 8704 + k * 272 + f * 16,
                     V + (size_t)(k0 + k) * DD + n0 + f * 4);
            }
            cp_commit();
            cp_wait<1>();
        } else {
            cp_wait<0>();
        }
        __syncthreads();

        const float* As  = (const float*)(smem + PA_OFF + buf * 18432);
        const float* Bsm = (const float*)(smem + PB_OFF + buf * 8704);
        #pragma unroll
        for (int s = 0; s < 4; s++) {
            uint32_t a[2][4];
            #pragma unroll
            for (int gi = 0; gi < 2; gi++) {
                int ra = w * 32 + gi * 16 + g;
                a[gi][0] = fbits(As[ra * 36 + 8 * s + tg]);
                a[gi][1] = fbits(As[(ra + 8) * 36 + 8 * s + tg]);
                a[gi][2] = fbits(As[ra * 36 + 8 * s + tg + 4]);
                a[gi][3] = fbits(As[(ra + 8) * 36 + 8 * s + tg + 4]);
            }
            #pragma unroll
            for (int j = 0; j < 8; j++) {
                uint32_t b0 = fbits(Bsm[(8 * s + tg) * 68 + 8 * j + g]);
                uint32_t b1 = fbits(Bsm[(8 * s + tg + 4) * 68 + 8 * j + g]);
                mma8(acc[0][j], a[0], b0, b1);
                mma8(acc[1][j], a[1], b0, b1);
            }
        }
        __syncthreads();
    }

    if (z == 2) {
        // V: stage (pitch 65 f32) then transposed bf16 store (b,h,dh,m)
        float* stg = (float*)smem;
        #pragma unroll
        for (int gi = 0; gi < 2; gi++) {
            int r0l = w * 32 + gi * 16 + g;
            #pragma unroll
            for (int j = 0; j < 8; j++) {
                int c0 = 8 * j + 2 * tg;
                float b0v = bias[n0 + c0], b1v = bias[n0 + c0 + 1];
                stg[r0l * 65 + c0]           = acc[gi][j][0] + b0v;
                stg[r0l * 65 + c0 + 1]       = acc[gi][j][1] + b1v;
                stg[(r0l + 8) * 65 + c0]     = acc[gi][j][2] + b0v;
                stg[(r0l + 8) * 65 + c0 + 1] = acc[gi][j][3] + b1v;
            }
        }
        __syncthreads();
        int c = tid & 63, half = tid >> 6;
        int bb = m0 >> 11, mloc = m0 & (MM - 1);
        __nv_bfloat16* o = g_v + ((size_t)(bb * HH + hd) * DHH + c) * MM + mloc + half * 64;
        #pragma unroll
        for (int e = 0; e < 8; e++) {
            int rb = half * 64 + e * 8;
            uint4 wv;
            wv.x = bf2(stg[rb * 65 + c],       stg[(rb + 1) * 65 + c]);
            wv.y = bf2(stg[(rb + 2) * 65 + c], stg[(rb + 3) * 65 + c]);
            wv.z = bf2(stg[(rb + 4) * 65 + c], stg[(rb + 5) * 65 + c]);
            wv.w = bf2(stg[(rb + 6) * 65 + c], stg[(rb + 7) * 65 + c]);
            *(uint4*)(o + e * 8) = wv;
        }
    } else {
        // q/k: bias + RoPE (table) + bf16 store
        float bl[4][4];
        #pragma unroll
        for (int jlo = 0; jlo < 4; jlo++) {
            int c0 = 8 * jlo + 2 * tg;
            bl[jlo][0] = bias[n0 + c0];
            bl[jlo][1] = bias[n0 + c0 + 1];
            bl[jlo][2] = bias[n0 + c0 + 32];
            bl[jlo][3] = bias[n0 + c0 + 33];
        }
        #pragma unroll
        for (int gi = 0; gi < 2; gi++) {
            int rbase = m0 + w * 32 + gi * 16 + g;
            #pragma unroll
            for (int hh = 0; hh < 2; hh++) {
                int row = rbase + 8 * hh;
                int iA = 2 * hh;
                int bb = row >> 11, mloc = row & (MM - 1);
                const float* cs = g_cs + (size_t)row * 64;
                __nv_bfloat16* o = dst + ((size_t)(bb * HH + hd) * MM + mloc) * DHH;
                #pragma unroll
                for (int jlo = 0; jlo < 4; jlo++) {
                    int c0 = 8 * jlo + 2 * tg;
                    float x0a = acc[gi][jlo][iA]         + bl[jlo][0];
                    float x0b = acc[gi][jlo][iA + 1]     + bl[jlo][1];
                    float x1a = acc[gi][jlo + 4][iA]     + bl[jlo][2];
                    float x1b = acc[gi][jlo + 4][iA + 1] + bl[jlo][3];
                    float2 cp = *(const float2*)&cs[c0];
                    float2 sp = *(const float2*)&cs[32 + c0];
                    *(__nv_bfloat162*)&o[c0] =
                        __floats2bfloat162_rn(x0a * cp.x - x1a * sp.x, x0b * cp.y - x1b * sp.y);
                    *(__nv_bfloat162*)&o[c0 + 32] =
                        __floats2bfloat162_rn(x0a * sp.x + x1a * cp.x, x0b * sp.y + x1b * cp.y);
                }
            }
        }
    }
}

// ---------------------------------------------------------------------------
// Attention: bf16 m16n8k16 mma.sync, fixed-offset softmax, register-resident
// P. CTA = 128 rows, 4 warps, 2 CTAs/SM. Keys in double-buffered 64-blocks.
// Smem: Q 128x72bf16 (18432) | K 2x9216 | Vt 2x9216 | mask 2x256 -> 55808 B
// ---------------------------------------------------------------------------
#define Q_OFF   0
#define K_OFF   18432
#define V_OFF   36864
#define MSK_OFF 55296
#define SMEM_TOTAL 55808
#define KV_STRIDE 9216
#define PITCHW 36   // 72 bf16 = 36 uint32 words per row

__global__ __launch_bounds__(128, 2) void attn_kernel(const int* __restrict__ amask,
                                                      float* __restrict__ out)
{
    extern __shared__ char smem[];
    const uint32_t sb = smem_u32(smem);
    const uint32_t* Qw = (const uint32_t*)(smem + Q_OFF);

    const int tid = threadIdx.x;
    const int w = tid >> 5, lane = tid & 31;
    const int g = lane >> 2, tg = lane & 3;
    const int bh = blockIdx.x;
    const int b = bh >> 4;
    const int m0 = blockIdx.y * 128;

    const __nv_bfloat16* qg = g_q + ((size_t)bh * MM + m0) * DHH;
    const __nv_bfloat16* kg = g_k + (size_t)bh * MM * DHH;
    const __nv_bfloat16* vg = g_v + (size_t)bh * DHH * MM;

    // ---- prologue: Q (128x64), K block0, Vt block0, mask0 ----
    #pragma unroll
    for (int e = 0; e < 8; e++) {
        int c = e * 128 + tid;
        int row = c >> 3, f = c & 7;
        cp16(sb + Q_OFF + row * 144 + f * 16, qg + row * 64 + f * 8);
    }
    #pragma unroll
    for (int e = 0; e < 4; e++) {
        int c = e * 128 + tid;
        int row = c >> 3, f = c & 7;
        cp16(sb + K_OFF + row * 144 + f * 16, kg + (size_t)row * 64 + f * 8);
        cp16(sb + V_OFF + row * 144 + f * 16, vg + (size_t)row * MM + f * 8);
    }
    if (tid < 16) cp16(sb + MSK_OFF + tid * 16, amask + (size_t)b * MM + tid * 4);
    cp_commit();
    cp_wait<0>();
    __syncthreads();

    float oc[2][8][4];
    #pragma unroll
    for (int gi = 0; gi < 2; gi++)
        #pragma unroll
        for (int j = 0; j < 8; j++)
            #pragma unroll
            for (int c = 0; c < 4; c++) oc[gi][j][c] = 0.0f;
    float ls[2][2] = {{0.f, 0.f}, {0.f, 0.f}};

    const float C1 = 0.18033688011112042f;   // (1/8)*log2(e)
    const float C2 = 43.28085122666891f;     // 30*log2(e)
    const int row0 = w * 32;

    for (int i = 0; i < 32; i++) {
        const int buf = i & 1, nb = buf ^ 1;

        if (i < 31) {
            int n1 = (i + 1) * 64;
            #pragma unroll
            for (int e = 0; e < 4; e++) {
                int c = e * 128 + tid;
                int row = c >> 3, f = c & 7;
                cp16(sb + K_OFF + nb * KV_STRIDE + row * 144 + f * 16,
                     kg + (size_t)(n1 + row) * 64 + f * 8);
                cp16(sb + V_OFF + nb * KV_STRIDE + row * 144 + f * 16,
                     vg + (size_t)row * MM + n1 + f * 8);
            }
            if (tid < 16) cp16(sb + MSK_OFF + nb * 256 + tid * 16,
                               amask + (size_t)b * MM + n1 + tid * 4);
            cp_commit();
        }

        const uint32_t* Kw = (const uint32_t*)(smem + K_OFF + buf * KV_STRIDE);
        const uint32_t* Vw = (const uint32_t*)(smem + V_OFF + buf * KV_STRIDE);

        // ---- S = Q(32 rows) x K^T(64 keys) ----
        float sc[2][8][4];
        #pragma unroll
        for (int gi = 0; gi < 2; gi++)
            #pragma unroll
            for (int j = 0; j < 8; j++)
                #pragma unroll
                for (int c = 0; c < 4; c++) sc[gi][j][c] = 0.0f;

        #pragma unroll
        for (int s = 0; s < 4; s++) {
            uint32_t a[2][4];
            #pragma unroll
            for (int gi = 0; gi < 2; gi++) {
                int ra = row0 + gi * 16 + g;
                a[gi][0] = Qw[ra * PITCHW + 8 * s + tg];
                a[gi][1] = Qw[(ra + 8) * PITCHW + 8 * s + tg];
                a[gi][2] = Qw[ra * PITCHW + 8 * s + tg + 4];
                a[gi][3] = Qw[(ra + 8) * PITCHW + 8 * s + tg + 4];
            }
            #pragma unroll
            for (int j = 0; j < 8; j++) {
                uint32_t b0 = Kw[(8 * j + g) * PITCHW + 8 * s + tg];
                uint32_t b1 = Kw[(8 * j + g) * PITCHW + 8 * s + tg + 4];
                mmab(sc[0][j], a[0], b0, b1);
                mmab(sc[1][j], a[1], b0, b1);
            }
        }

        // ---- softmax: p = exp(s/8 - 30); pack into A-frags ----
        const int* msk = (const int*)(smem + MSK_OFF + buf * 256);
        uint32_t pa[2][4][4];
        #pragma unroll
        for (int j = 0; j < 8; j++) {
            int2 mv = *(const int2*)&msk[8 * j + 2 * tg];
            #pragma unroll
            for (int gi = 0; gi < 2; gi++) {
                float p0 = ex2f(fmaf(sc[gi][j][0], C1, -C2)); if (!mv.x) p0 = 0.f;
                float p1 = ex2f(fmaf(sc[gi][j][1], C1, -C2)); if (!mv.y) p1 = 0.f;
                float p2 = ex2f(fmaf(sc[gi][j][2], C1, -C2)); if (!mv.x) p2 = 0.f;
                float p3 = ex2f(fmaf(sc[gi][j][3], C1, -C2)); if (!mv.y) p3 = 0.f;
                ls[gi][0] += p0 + p1;
                ls[gi][1] += p2 + p3;
                int s = j >> 1;
                if ((j & 1) == 0) {
                    pa[gi][s][0] = bf2(p0, p1);
                    pa[gi][s][1] = bf2(p2, p3);
                } else {
                    pa[gi][s][2] = bf2(p0, p1);
                    pa[gi][s][3] = bf2(p2, p3);
                }
            }
        }

        // ---- O += P x V ----
        #pragma unroll
        for (int s = 0; s < 4; s++) {
            #pragma unroll
            for (int j = 0; j < 8; j++) {
                uint32_t b0 = Vw[(8 * j + g) * PITCHW + 8 * s + tg];
                uint32_t b1 = Vw[(8 * j + g) * PITCHW + 8 * s + tg + 4];
                mmab(oc[0][j], pa[0][s], b0, b1);
                mmab(oc[1][j], pa[1][s], b0, b1);
            }
        }

        cp_wait<0>();
        __syncthreads();
    }

    // ---- finalize ----
    #pragma unroll
    for (int gi = 0; gi < 2; gi++) {
        float l0 = ls[gi][0];
        l0 += __shfl_xor_sync(0xffffffffu, l0, 1);
        l0 += __shfl_xor_sync(0xffffffffu, l0, 2);
        float l1 = ls[gi][1];
        l1 += __shfl_xor_sync(0xffffffffu, l1, 1);
        l1 += __shfl_xor_sync(0xffffffffu, l1, 2);
        float i0 = (l0 > 0.f) ? (1.0f / l0) : 0.f;
        float i1 = (l1 > 0.f) ? (1.0f / l1) : 0.f;
        int row = row0 + gi * 16 + g;
        float* o0 = out + ((size_t)bh * MM + m0 + row) * DHH;
        float* o1 = out + ((size_t)bh * MM + m0 + row + 8) * DHH;
        #pragma unroll
        for (int j = 0; j < 8; j++) {
            *(float2*)(o0 + 8 * j + 2 * tg) = make_float2(oc[gi][j][0] * i0, oc[gi][j][1] * i0);
            *(float2*)(o1 + 8 * j + 2 * tg) = make_float2(oc[gi][j][2] * i1, oc[gi][j][3] * i1);
        }
    }
}

extern "C" void kernel_launch(void* const* d_in, const int* in_sizes, int n_in,
                              void* d_out, int out_size) {
    const float* Pq = (const float*)d_in[0];
    const float* Pk = (const float*)d_in[1];
    const float* Pv = (const float*)d_in[2];
    const float* Vq = (const float*)d_in[3];
    const float* Vk = (const float*)d_in[4];
    const float* Vv = (const float*)d_in[5];
    const float* bq = (const float*)d_in[6];
    const float* bk = (const float*)d_in[7];
    const float* bv = (const float*)d_in[8];
    const int* amask = (const int*)d_in[9];
    const int* pos   = (const int*)d_in[10];

    static int smem_set = 0;
    if (!smem_set) {
        cudaFuncSetAttribute(attn_kernel, cudaFuncAttributeMaxDynamicSharedMemorySize, SMEM_TOTAL);
        cudaFuncSetAttribute(proj_kernel, cudaFuncAttributeMaxDynamicSharedMemorySize, PROJ_SMEM);
        smem_set = 1;
    }

    rope_kernel<<<BB * MM * 32 / 256, 256>>>(pos);

    dim3 pg(HH, (BB * MM) / 128, 3);         // 16 x 32 x 3
    proj_kernel<<<pg, 128, PROJ_SMEM>>>(Pq, Pk, Pv, Vq, Vk, Vv, bq, bk, bv);

    dim3 ag(BB * HH, MM / 128);              // 32 x 16
    attn_kernel<<<ag, 128, SMEM_TOTAL>>>(amask, (float*)d_out);
}